// round 2
// baseline (speedup 1.0000x reference)
#include <cuda_runtime.h>
#include <math.h>

#define NB 8
#define NT 2048
#define NC 1024
#define NH 256

// scratch for projected Q, K, V (48 MB total)
__device__ float g_Q[NB * NT * NH];
__device__ float g_K[NB * NT * NH];
__device__ float g_V[NB * NT * NH];

typedef unsigned long long u64;

__device__ __forceinline__ u64 pack2(float lo, float hi) {
    u64 r; asm("mov.b64 %0, {%1,%2};" : "=l"(r) : "f"(lo), "f"(hi)); return r;
}
__device__ __forceinline__ void fma2(u64 &d, u64 a, u64 b) {
    asm("fma.rn.f32x2 %0, %1, %2, %3;" : "=l"(d) : "l"(a), "l"(b), "l"(d));
}
__device__ __forceinline__ void mul2(u64 &d, u64 b) {
    asm("mul.rn.f32x2 %0, %1, %2;" : "=l"(d) : "l"(d), "l"(b));
}
__device__ __forceinline__ float2 unpack2(u64 v) {
    float lo, hi; asm("mov.b64 {%0,%1}, %2;" : "=f"(lo), "=f"(hi) : "l"(v));
    return make_float2(lo, hi);
}

// ---------------- Kernel 1: QKV projection  out = x @ W ----------------
// tile 128(M) x 128(N), BK=8, 256 threads, 8x8 micro via f32x2
__global__ void __launch_bounds__(256, 2)
qkv_kernel(const float* __restrict__ x, const float* __restrict__ Wq,
           const float* __restrict__ Wk, const float* __restrict__ Wv) {
    __shared__ float As[8][128];   // [k][m]
    __shared__ float Bs[8][128];   // [k][n]

    const int z = blockIdx.z;
    const float* W = (z == 0) ? Wq : ((z == 1) ? Wk : Wv);
    float* out = (z == 0) ? g_Q : ((z == 1) ? g_K : g_V);

    const int m0 = blockIdx.y * 128;
    const int n0 = blockIdx.x * 128;
    const int tid = threadIdx.x;
    const int tx = tid & 15;    // n-groups
    const int ty = tid >> 4;    // m-groups

    u64 acc[8][4];
#pragma unroll
    for (int i = 0; i < 8; i++)
#pragma unroll
        for (int j = 0; j < 4; j++) acc[i][j] = 0ull;

    const int arow = tid >> 1;          // 0..127
    const int ac4  = (tid & 1) * 4;     // 0 or 4
    const int brow = tid >> 5;          // 0..7
    const int bc4  = (tid & 31) * 4;    // 0..124
    const float* xg = x + (size_t)(m0 + arow) * NC + ac4;
    const float* wg = W + (size_t)brow * NH + n0 + bc4;

    for (int k0 = 0; k0 < NC; k0 += 8) {
        float4 av = *(const float4*)(xg + k0);
        float4 bv = *(const float4*)(wg + (size_t)k0 * NH);
        __syncthreads();
        As[ac4 + 0][arow] = av.x;
        As[ac4 + 1][arow] = av.y;
        As[ac4 + 2][arow] = av.z;
        As[ac4 + 3][arow] = av.w;
        *(float4*)&Bs[brow][bc4] = bv;
        __syncthreads();
#pragma unroll
        for (int kk = 0; kk < 8; kk++) {
            float4 a0 = *(const float4*)&As[kk][ty * 8];
            float4 a1 = *(const float4*)&As[kk][ty * 8 + 4];
            ulonglong2 b0 = *(const ulonglong2*)&Bs[kk][tx * 4];       // cols 4tx..+3
            ulonglong2 b1 = *(const ulonglong2*)&Bs[kk][tx * 4 + 64];  // cols +64
            float a[8] = {a0.x, a0.y, a0.z, a0.w, a1.x, a1.y, a1.z, a1.w};
#pragma unroll
            for (int i = 0; i < 8; i++) {
                u64 ap = pack2(a[i], a[i]);
                fma2(acc[i][0], ap, b0.x);
                fma2(acc[i][1], ap, b0.y);
                fma2(acc[i][2], ap, b1.x);
                fma2(acc[i][3], ap, b1.y);
            }
        }
    }

#pragma unroll
    for (int i = 0; i < 8; i++) {
        float2 p0 = unpack2(acc[i][0]), p1 = unpack2(acc[i][1]);
        float2 p2 = unpack2(acc[i][2]), p3 = unpack2(acc[i][3]);
        float* orow = out + (size_t)(m0 + ty * 8 + i) * NH + n0;
        *(float4*)(orow + tx * 4)      = make_float4(p0.x, p0.y, p1.x, p1.y);
        *(float4*)(orow + tx * 4 + 64) = make_float4(p2.x, p2.y, p3.x, p3.y);
    }
}

// ---------------- Kernel 2: causal flash attention ----------------
// One block per (batch, 64-row Q tile). 256 threads as 16(tx) x 16(ty).
// Qt/Kt stored transposed [h][row] for conflict-free GEMM-style reads.
#define ATTN_SMEM ((3 * 16384 + 4096) * 4)

__global__ void __launch_bounds__(256, 1)
attn_kernel(float* __restrict__ out) {
    extern __shared__ float sm[];
    float* Qt = sm;              // [256][64]  (scaled by 16)
    float* Kt = sm + 16384;      // [256][64]
    float* Vs = sm + 32768;      // [64][256]
    float* Ps = sm + 49152;      // [64][64]

    const int b   = blockIdx.y;
    const int qt  = 31 - blockIdx.x;   // big-work blocks first
    const int tid = threadIdx.x;
    const int tx  = tid & 15;
    const int ty  = tid >> 4;

    const float* Qg = g_Q + ((size_t)b * NT + qt * 64) * NH;
    const float* Kb = g_K + (size_t)b * NT * NH;
    const float* Vb = g_V + (size_t)b * NT * NH;

    const int li = tid & 63;    // row/col within tile for loads
    const int hb = tid >> 6;    // 0..3

    // load Q tile transposed, folding in the *sqrt(H)=16 logit scale
#pragma unroll
    for (int it = 0; it < 16; it++) {
        int h4 = (hb + 4 * it) * 4;
        float4 v = *(const float4*)(Qg + (size_t)li * NH + h4);
        Qt[(h4 + 0) * 64 + li] = v.x * 16.0f;
        Qt[(h4 + 1) * 64 + li] = v.y * 16.0f;
        Qt[(h4 + 2) * 64 + li] = v.z * 16.0f;
        Qt[(h4 + 3) * 64 + li] = v.w * 16.0f;
    }

    float m_run[4], l_run[4];
#pragma unroll
    for (int i = 0; i < 4; i++) { m_run[i] = -1e30f; l_run[i] = 0.0f; }

    u64 oacc[4][8];   // rows 4ty+ii; col pairs at 4tx(+64u)
#pragma unroll
    for (int i = 0; i < 4; i++)
#pragma unroll
        for (int j = 0; j < 8; j++) oacc[i][j] = 0ull;

    const int nIter = qt + 1;
    for (int itr = 0; itr < nIter; itr++) {
        const int j0 = itr * 64;
        __syncthreads();   // prior reads of Kt/Vs/Ps complete

        // load K tile transposed
#pragma unroll
        for (int it = 0; it < 16; it++) {
            int h4 = (hb + 4 * it) * 4;
            float4 v = *(const float4*)(Kb + (size_t)(j0 + li) * NH + h4);
            Kt[(h4 + 0) * 64 + li] = v.x;
            Kt[(h4 + 1) * 64 + li] = v.y;
            Kt[(h4 + 2) * 64 + li] = v.z;
            Kt[(h4 + 3) * 64 + li] = v.w;
        }
        // load V tile natural
#pragma unroll
        for (int it = 0; it < 16; it++) {
            int idx = it * 256 + tid;
            int j = idx >> 6, g4 = (idx & 63) * 4;
            *(float4*)&Vs[j * 256 + g4] =
                *(const float4*)(Vb + (size_t)(j0 + j) * NH + g4);
        }
        __syncthreads();

        // ---- S = Q K^T (4x4 per thread, f32x2 over j-pairs) ----
        u64 sacc[4][2];
#pragma unroll
        for (int i = 0; i < 4; i++) { sacc[i][0] = 0ull; sacc[i][1] = 0ull; }
#pragma unroll 8
        for (int h = 0; h < 256; h++) {
            float4 q = *(const float4*)&Qt[h * 64 + 4 * ty];
            ulonglong2 kp = *(const ulonglong2*)&Kt[h * 64 + 4 * tx];
            float qa[4] = {q.x, q.y, q.z, q.w};
#pragma unroll
            for (int i = 0; i < 4; i++) {
                u64 qp = pack2(qa[i], qa[i]);
                fma2(sacc[i][0], qp, kp.x);
                fma2(sacc[i][1], qp, kp.y);
            }
        }

        float s[4][4];
#pragma unroll
        for (int i = 0; i < 4; i++) {
            float2 p0 = unpack2(sacc[i][0]), p1 = unpack2(sacc[i][1]);
            s[i][0] = p0.x; s[i][1] = p0.y; s[i][2] = p1.x; s[i][3] = p1.y;
        }

        // causal mask (diagonal tile only)
        if (j0 == qt * 64) {
#pragma unroll
            for (int i = 0; i < 4; i++)
#pragma unroll
                for (int j = 0; j < 4; j++)
                    if (4 * tx + j > 4 * ty + i) s[i][j] = -1e30f;
        }

        // ---- online softmax (stats replicated across the 16 tx lanes) ----
        float p[4][4];
#pragma unroll
        for (int i = 0; i < 4; i++) {
            float mloc = fmaxf(fmaxf(s[i][0], s[i][1]), fmaxf(s[i][2], s[i][3]));
#pragma unroll
            for (int off = 1; off < 16; off <<= 1)
                mloc = fmaxf(mloc, __shfl_xor_sync(0xffffffffu, mloc, off, 16));
            float m_new = fmaxf(m_run[i], mloc);
            float scale = __expf(m_run[i] - m_new);
            float rsum = 0.0f;
#pragma unroll
            for (int j = 0; j < 4; j++) {
                p[i][j] = __expf(s[i][j] - m_new);
                rsum += p[i][j];
            }
#pragma unroll
            for (int off = 1; off < 16; off <<= 1)
                rsum += __shfl_xor_sync(0xffffffffu, rsum, off, 16);
            l_run[i] = l_run[i] * scale + rsum;
            m_run[i] = m_new;
            u64 sc2 = pack2(scale, scale);
#pragma unroll
            for (int u = 0; u < 8; u++) mul2(oacc[i][u], sc2);
        }

        // stage P to smem
#pragma unroll
        for (int i = 0; i < 4; i++)
            *(float4*)&Ps[(4 * ty + i) * 64 + 4 * tx] =
                make_float4(p[i][0], p[i][1], p[i][2], p[i][3]);
        __syncthreads();

        // ---- O += P V ----
#pragma unroll 4
        for (int j = 0; j < 64; j++) {
            ulonglong2 v0 = *(const ulonglong2*)&Vs[j * 256 + 4 * tx];
            ulonglong2 v1 = *(const ulonglong2*)&Vs[j * 256 + 4 * tx + 64];
            ulonglong2 v2 = *(const ulonglong2*)&Vs[j * 256 + 4 * tx + 128];
            ulonglong2 v3 = *(const ulonglong2*)&Vs[j * 256 + 4 * tx + 192];
#pragma unroll
            for (int i = 0; i < 4; i++) {
                u64 pp = pack2(Ps[(4 * ty + i) * 64 + j], Ps[(4 * ty + i) * 64 + j]);
                fma2(oacc[i][0], pp, v0.x); fma2(oacc[i][1], pp, v0.y);
                fma2(oacc[i][2], pp, v1.x); fma2(oacc[i][3], pp, v1.y);
                fma2(oacc[i][4], pp, v2.x); fma2(oacc[i][5], pp, v2.y);
                fma2(oacc[i][6], pp, v3.x); fma2(oacc[i][7], pp, v3.y);
            }
        }
    }

    // ---- normalize + write ----
#pragma unroll
    for (int i = 0; i < 4; i++) {
        float inv = 1.0f / l_run[i];
        size_t row = (size_t)b * NT + qt * 64 + 4 * ty + i;
        float* orow = out + row * NH;
#pragma unroll
        for (int u = 0; u < 4; u++) {
            float2 a = unpack2(oacc[i][2 * u]);
            float2 c = unpack2(oacc[i][2 * u + 1]);
            *(float4*)(orow + 4 * tx + 64 * u) =
                make_float4(a.x * inv, a.y * inv, c.x * inv, c.y * inv);
        }
    }
}

extern "C" void kernel_launch(void* const* d_in, const int* in_sizes, int n_in,
                              void* d_out, int out_size) {
    const float* x  = (const float*)d_in[0];
    const float* Wq = (const float*)d_in[1];
    const float* Wk = (const float*)d_in[2];
    const float* Wv = (const float*)d_in[3];
    float* out = (float*)d_out;

    cudaFuncSetAttribute(attn_kernel,
                         cudaFuncAttributeMaxDynamicSharedMemorySize, ATTN_SMEM);

    qkv_kernel<<<dim3(2, 128, 3), 256>>>(x, Wq, Wk, Wv);
    attn_kernel<<<dim3(32, NB), 256, ATTN_SMEM>>>(out);
}

// round 3
// speedup vs baseline: 1.0655x; 1.0655x over previous
#include <cuda_runtime.h>
#include <math.h>

#define NB 8
#define NT 2048
#define NC 1024
#define NH 256

// scratch for projected Q, K, V (48 MB total)
__device__ float g_Q[NB * NT * NH];
__device__ float g_K[NB * NT * NH];
__device__ float g_V[NB * NT * NH];

typedef unsigned long long u64;

__device__ __forceinline__ u64 pack2(float lo, float hi) {
    u64 r; asm("mov.b64 %0, {%1,%2};" : "=l"(r) : "f"(lo), "f"(hi)); return r;
}
__device__ __forceinline__ void fma2(u64 &d, u64 a, u64 b) {
    asm("fma.rn.f32x2 %0, %1, %2, %3;" : "=l"(d) : "l"(a), "l"(b), "l"(d));
}
__device__ __forceinline__ void mul2(u64 &d, u64 b) {
    asm("mul.rn.f32x2 %0, %1, %2;" : "=l"(d) : "l"(d), "l"(b));
}
__device__ __forceinline__ float2 unpack2(u64 v) {
    float lo, hi; asm("mov.b64 {%0,%1}, %2;" : "=f"(lo), "=f"(hi) : "l"(v));
    return make_float2(lo, hi);
}

// ---------------- Kernel 1: QKV projection  out = x @ W ----------------
// tile 128(M) x 128(N), BK=8, 256 threads, 8x8 micro via f32x2.
// Global loads for tile k0+8 are issued before computing tile k0 (reg prefetch).
__global__ void __launch_bounds__(256, 2)
qkv_kernel(const float* __restrict__ x, const float* __restrict__ Wq,
           const float* __restrict__ Wk, const float* __restrict__ Wv) {
    __shared__ float As[8][128];   // [k][m]
    __shared__ float Bs[8][128];   // [k][n]

    const int z = blockIdx.z;
    const float* W = (z == 0) ? Wq : ((z == 1) ? Wk : Wv);
    float* out = (z == 0) ? g_Q : ((z == 1) ? g_K : g_V);

    const int m0 = blockIdx.y * 128;
    const int n0 = blockIdx.x * 128;
    const int tid = threadIdx.x;
    const int tx = tid & 15;    // n-groups
    const int ty = tid >> 4;    // m-groups

    u64 acc[8][4];
#pragma unroll
    for (int i = 0; i < 8; i++)
#pragma unroll
        for (int j = 0; j < 4; j++) acc[i][j] = 0ull;

    const int arow = tid >> 1;          // 0..127
    const int ac4  = (tid & 1) * 4;     // 0 or 4
    const int brow = tid >> 5;          // 0..7
    const int bc4  = (tid & 31) * 4;    // 0..124
    const float* xg = x + (size_t)(m0 + arow) * NC + ac4;
    const float* wg = W + (size_t)brow * NH + n0 + bc4;

    float4 av = *(const float4*)(xg);
    float4 bv = *(const float4*)(wg);

    for (int k0 = 0; k0 < NC; k0 += 8) {
        __syncthreads();
        As[ac4 + 0][arow] = av.x;
        As[ac4 + 1][arow] = av.y;
        As[ac4 + 2][arow] = av.z;
        As[ac4 + 3][arow] = av.w;
        *(float4*)&Bs[brow][bc4] = bv;
        __syncthreads();
        if (k0 + 8 < NC) {   // prefetch next tile while computing this one
            av = *(const float4*)(xg + k0 + 8);
            bv = *(const float4*)(wg + (size_t)(k0 + 8) * NH);
        }
#pragma unroll
        for (int kk = 0; kk < 8; kk++) {
            float4 a0 = *(const float4*)&As[kk][ty * 8];
            float4 a1 = *(const float4*)&As[kk][ty * 8 + 4];
            ulonglong2 b0 = *(const ulonglong2*)&Bs[kk][tx * 4];       // cols 4tx..+3
            ulonglong2 b1 = *(const ulonglong2*)&Bs[kk][tx * 4 + 64];  // cols +64
            float a[8] = {a0.x, a0.y, a0.z, a0.w, a1.x, a1.y, a1.z, a1.w};
#pragma unroll
            for (int i = 0; i < 8; i++) {
                u64 ap = pack2(a[i], a[i]);
                fma2(acc[i][0], ap, b0.x);
                fma2(acc[i][1], ap, b0.y);
                fma2(acc[i][2], ap, b1.x);
                fma2(acc[i][3], ap, b1.y);
            }
        }
    }

#pragma unroll
    for (int i = 0; i < 8; i++) {
        float2 p0 = unpack2(acc[i][0]), p1 = unpack2(acc[i][1]);
        float2 p2 = unpack2(acc[i][2]), p3 = unpack2(acc[i][3]);
        float* orow = out + (size_t)(m0 + ty * 8 + i) * NH + n0;
        *(float4*)(orow + tx * 4)      = make_float4(p0.x, p0.y, p1.x, p1.y);
        *(float4*)(orow + tx * 4 + 64) = make_float4(p2.x, p2.y, p3.x, p3.y);
    }
}

// ---------------- Kernel 2: causal flash attention ----------------
// 512 threads/block (16 warps/SM). Each block handles TWO q-tiles,
// (31-px) and (px), so every block does exactly 33 tile-iterations:
// one perfectly balanced wave of 128 blocks.
// Thread tile: 2 rows (2ty, 2ty+1) x 16 cols (4tx..+3, +64,+128,+192).
#define ATTN_SMEM ((3 * 16384 + 4096) * 4)

__global__ void __launch_bounds__(512, 1)
attn_kernel(float* __restrict__ out) {
    extern __shared__ float sm[];
    float* Qt = sm;              // [256][64]  transposed, scaled by 16
    float* Kt = sm + 16384;      // [256][64]  transposed
    float* Vs = sm + 32768;      // [64][256]  natural
    float* Ps = sm + 49152;      // [64][64]

    const int b   = blockIdx.y;
    const int px  = blockIdx.x;        // 0..15
    const int tid = threadIdx.x;
    const int tx  = tid & 15;
    const int ty  = tid >> 4;          // 0..31

    const float* Kb = g_K + (size_t)b * NT * NH;
    const float* Vb = g_V + (size_t)b * NT * NH;

    const int li = tid & 63;    // row within tile for transposed loads
    const int hb = tid >> 6;    // 0..7

    for (int half = 0; half < 2; half++) {
        const int qt = (half == 0) ? (31 - px) : px;
        const float* Qg = g_Q + ((size_t)b * NT + qt * 64) * NH;

        __syncthreads();   // protect Qt from previous half's readers

        // load Q tile transposed, folding in the *sqrt(H)=16 logit scale
#pragma unroll
        for (int it = 0; it < 8; it++) {
            int h4 = (hb + 8 * it) * 4;
            float4 v = *(const float4*)(Qg + (size_t)li * NH + h4);
            Qt[(h4 + 0) * 64 + li] = v.x * 16.0f;
            Qt[(h4 + 1) * 64 + li] = v.y * 16.0f;
            Qt[(h4 + 2) * 64 + li] = v.z * 16.0f;
            Qt[(h4 + 3) * 64 + li] = v.w * 16.0f;
        }

        float m_run[2], l_run[2];
#pragma unroll
        for (int i = 0; i < 2; i++) { m_run[i] = -1e30f; l_run[i] = 0.0f; }

        u64 oacc[2][8];
#pragma unroll
        for (int i = 0; i < 2; i++)
#pragma unroll
            for (int j = 0; j < 8; j++) oacc[i][j] = 0ull;

        const int nIter = qt + 1;
        for (int itr = 0; itr < nIter; itr++) {
            const int j0 = itr * 64;
            __syncthreads();   // prior reads of Kt/Vs/Ps complete

            // load K tile transposed
#pragma unroll
            for (int it = 0; it < 8; it++) {
                int h4 = (hb + 8 * it) * 4;
                float4 v = *(const float4*)(Kb + (size_t)(j0 + li) * NH + h4);
                Kt[(h4 + 0) * 64 + li] = v.x;
                Kt[(h4 + 1) * 64 + li] = v.y;
                Kt[(h4 + 2) * 64 + li] = v.z;
                Kt[(h4 + 3) * 64 + li] = v.w;
            }
            // load V tile natural
#pragma unroll
            for (int it = 0; it < 8; it++) {
                int idx = it * 512 + tid;
                int j = idx >> 6, g4 = (idx & 63) * 4;
                *(float4*)&Vs[j * 256 + g4] =
                    *(const float4*)(Vb + (size_t)(j0 + j) * NH + g4);
            }
            __syncthreads();

            // ---- S = Q K^T (2x4 per thread, f32x2 over j-pairs) ----
            u64 sacc[2][2];
#pragma unroll
            for (int i = 0; i < 2; i++) { sacc[i][0] = 0ull; sacc[i][1] = 0ull; }
#pragma unroll 8
            for (int h = 0; h < 256; h++) {
                float2 q = *(const float2*)&Qt[h * 64 + 2 * ty];
                ulonglong2 kp = *(const ulonglong2*)&Kt[h * 64 + 4 * tx];
                u64 q0 = pack2(q.x, q.x);
                u64 q1 = pack2(q.y, q.y);
                fma2(sacc[0][0], q0, kp.x);
                fma2(sacc[0][1], q0, kp.y);
                fma2(sacc[1][0], q1, kp.x);
                fma2(sacc[1][1], q1, kp.y);
            }

            float s[2][4];
#pragma unroll
            for (int i = 0; i < 2; i++) {
                float2 p0 = unpack2(sacc[i][0]), p1 = unpack2(sacc[i][1]);
                s[i][0] = p0.x; s[i][1] = p0.y; s[i][2] = p1.x; s[i][3] = p1.y;
            }

            // causal mask (diagonal tile only)
            if (j0 == qt * 64) {
#pragma unroll
                for (int i = 0; i < 2; i++)
#pragma unroll
                    for (int j = 0; j < 4; j++)
                        if (4 * tx + j > 2 * ty + i) s[i][j] = -1e30f;
            }

            // ---- online softmax (stats replicated across the 16 tx lanes) ----
            float p[2][4];
#pragma unroll
            for (int i = 0; i < 2; i++) {
                float mloc = fmaxf(fmaxf(s[i][0], s[i][1]), fmaxf(s[i][2], s[i][3]));
#pragma unroll
                for (int off = 1; off < 16; off <<= 1)
                    mloc = fmaxf(mloc, __shfl_xor_sync(0xffffffffu, mloc, off, 16));
                float m_new = fmaxf(m_run[i], mloc);
                float scale = __expf(m_run[i] - m_new);
                float rsum = 0.0f;
#pragma unroll
                for (int j = 0; j < 4; j++) {
                    p[i][j] = __expf(s[i][j] - m_new);
                    rsum += p[i][j];
                }
#pragma unroll
                for (int off = 1; off < 16; off <<= 1)
                    rsum += __shfl_xor_sync(0xffffffffu, rsum, off, 16);
                l_run[i] = l_run[i] * scale + rsum;
                m_run[i] = m_new;
                u64 sc2 = pack2(scale, scale);
#pragma unroll
                for (int u = 0; u < 8; u++) mul2(oacc[i][u], sc2);
            }

            // stage P to smem
#pragma unroll
            for (int i = 0; i < 2; i++)
                *(float4*)&Ps[(2 * ty + i) * 64 + 4 * tx] =
                    make_float4(p[i][0], p[i][1], p[i][2], p[i][3]);
            __syncthreads();

            // ---- O += P V ----
#pragma unroll 4
            for (int j = 0; j < 64; j++) {
                ulonglong2 v0 = *(const ulonglong2*)&Vs[j * 256 + 4 * tx];
                ulonglong2 v1 = *(const ulonglong2*)&Vs[j * 256 + 4 * tx + 64];
                ulonglong2 v2 = *(const ulonglong2*)&Vs[j * 256 + 4 * tx + 128];
                ulonglong2 v3 = *(const ulonglong2*)&Vs[j * 256 + 4 * tx + 192];
#pragma unroll
                for (int i = 0; i < 2; i++) {
                    float pv = Ps[(2 * ty + i) * 64 + j];
                    u64 pp = pack2(pv, pv);
                    fma2(oacc[i][0], pp, v0.x); fma2(oacc[i][1], pp, v0.y);
                    fma2(oacc[i][2], pp, v1.x); fma2(oacc[i][3], pp, v1.y);
                    fma2(oacc[i][4], pp, v2.x); fma2(oacc[i][5], pp, v2.y);
                    fma2(oacc[i][6], pp, v3.x); fma2(oacc[i][7], pp, v3.y);
                }
            }
        }

        // ---- normalize + write ----
#pragma unroll
        for (int i = 0; i < 2; i++) {
            float inv = 1.0f / l_run[i];
            size_t row = (size_t)b * NT + qt * 64 + 2 * ty + i;
            float* orow = out + row * NH;
#pragma unroll
            for (int u = 0; u < 4; u++) {
                float2 a = unpack2(oacc[i][2 * u]);
                float2 c = unpack2(oacc[i][2 * u + 1]);
                *(float4*)(orow + 4 * tx + 64 * u) =
                    make_float4(a.x * inv, a.y * inv, c.x * inv, c.y * inv);
            }
        }
    }
}

extern "C" void kernel_launch(void* const* d_in, const int* in_sizes, int n_in,
                              void* d_out, int out_size) {
    const float* x  = (const float*)d_in[0];
    const float* Wq = (const float*)d_in[1];
    const float* Wk = (const float*)d_in[2];
    const float* Wv = (const float*)d_in[3];
    float* out = (float*)d_out;

    cudaFuncSetAttribute(attn_kernel,
                         cudaFuncAttributeMaxDynamicSharedMemorySize, ATTN_SMEM);

    qkv_kernel<<<dim3(2, 128, 3), 256>>>(x, Wq, Wk, Wv);
    attn_kernel<<<dim3(16, NB), 512, ATTN_SMEM>>>(out);
}

// round 4
// speedup vs baseline: 1.0688x; 1.0031x over previous
#include <cuda_runtime.h>
#include <math.h>

#define NB 8
#define NT 2048
#define NC 1024
#define NH 256

// scratch for projected Q, K, V (48 MB total)
__device__ float g_Q[NB * NT * NH];
__device__ float g_K[NB * NT * NH];
__device__ float g_V[NB * NT * NH];

typedef unsigned long long u64;

__device__ __forceinline__ u64 pack2(float lo, float hi) {
    u64 r; asm("mov.b64 %0, {%1,%2};" : "=l"(r) : "f"(lo), "f"(hi)); return r;
}
__device__ __forceinline__ void fma2(u64 &d, u64 a, u64 b) {
    asm("fma.rn.f32x2 %0, %1, %2, %3;" : "=l"(d) : "l"(a), "l"(b), "l"(d));
}
__device__ __forceinline__ void mul2(u64 &d, u64 b) {
    asm("mul.rn.f32x2 %0, %1, %2;" : "=l"(d) : "l"(d), "l"(b));
}
__device__ __forceinline__ float2 unpack2(u64 v) {
    float lo, hi; asm("mov.b64 {%0,%1}, %2;" : "=f"(lo), "=f"(hi) : "l"(v));
    return make_float2(lo, hi);
}

// ---------------- Kernel 1: QKV projection  out = x @ W ----------------
// tile 128(M) x 128(N), BK=8, 256 threads, 8x8 micro via f32x2.
// Global loads for tile k0+8 are issued before computing tile k0 (reg prefetch).
__global__ void __launch_bounds__(256, 2)
qkv_kernel(const float* __restrict__ x, const float* __restrict__ Wq,
           const float* __restrict__ Wk, const float* __restrict__ Wv) {
    __shared__ float As[8][128];   // [k][m]
    __shared__ float Bs[8][128];   // [k][n]

    const int z = blockIdx.z;
    const float* W = (z == 0) ? Wq : ((z == 1) ? Wk : Wv);
    float* out = (z == 0) ? g_Q : ((z == 1) ? g_K : g_V);

    const int m0 = blockIdx.y * 128;
    const int n0 = blockIdx.x * 128;
    const int tid = threadIdx.x;
    const int tx = tid & 15;    // n-groups
    const int ty = tid >> 4;    // m-groups

    u64 acc[8][4];
#pragma unroll
    for (int i = 0; i < 8; i++)
#pragma unroll
        for (int j = 0; j < 4; j++) acc[i][j] = 0ull;

    const int arow = tid >> 1;          // 0..127
    const int ac4  = (tid & 1) * 4;     // 0 or 4
    const int brow = tid >> 5;          // 0..7
    const int bc4  = (tid & 31) * 4;    // 0..124
    const float* xg = x + (size_t)(m0 + arow) * NC + ac4;
    const float* wg = W + (size_t)brow * NH + n0 + bc4;

    float4 av = *(const float4*)(xg);
    float4 bv = *(const float4*)(wg);

    for (int k0 = 0; k0 < NC; k0 += 8) {
        __syncthreads();
        As[ac4 + 0][arow] = av.x;
        As[ac4 + 1][arow] = av.y;
        As[ac4 + 2][arow] = av.z;
        As[ac4 + 3][arow] = av.w;
        *(float4*)&Bs[brow][bc4] = bv;
        __syncthreads();
        if (k0 + 8 < NC) {   // prefetch next tile while computing this one
            av = *(const float4*)(xg + k0 + 8);
            bv = *(const float4*)(wg + (size_t)(k0 + 8) * NH);
        }
#pragma unroll
        for (int kk = 0; kk < 8; kk++) {
            float4 a0 = *(const float4*)&As[kk][ty * 8];
            float4 a1 = *(const float4*)&As[kk][ty * 8 + 4];
            ulonglong2 b0 = *(const ulonglong2*)&Bs[kk][tx * 4];       // cols 4tx..+3
            ulonglong2 b1 = *(const ulonglong2*)&Bs[kk][tx * 4 + 64];  // cols +64
            float a[8] = {a0.x, a0.y, a0.z, a0.w, a1.x, a1.y, a1.z, a1.w};
#pragma unroll
            for (int i = 0; i < 8; i++) {
                u64 ap = pack2(a[i], a[i]);
                fma2(acc[i][0], ap, b0.x);
                fma2(acc[i][1], ap, b0.y);
                fma2(acc[i][2], ap, b1.x);
                fma2(acc[i][3], ap, b1.y);
            }
        }
    }

#pragma unroll
    for (int i = 0; i < 8; i++) {
        float2 p0 = unpack2(acc[i][0]), p1 = unpack2(acc[i][1]);
        float2 p2 = unpack2(acc[i][2]), p3 = unpack2(acc[i][3]);
        float* orow = out + (size_t)(m0 + ty * 8 + i) * NH + n0;
        *(float4*)(orow + tx * 4)      = make_float4(p0.x, p0.y, p1.x, p1.y);
        *(float4*)(orow + tx * 4 + 64) = make_float4(p2.x, p2.y, p3.x, p3.y);
    }
}

// ---------------- Kernel 2: causal flash attention ----------------
// 512 threads/block (16 warps/SM). Each block handles TWO q-tiles,
// (31-px) and (px), so every block does exactly 33 tile-iterations:
// one perfectly balanced wave of 128 blocks.
// Thread tile: 2 rows (2ty, 2ty+1) x 16 cols (4tx..+3, +64,+128,+192).
#define ATTN_SMEM ((3 * 16384 + 4096) * 4)

__global__ void __launch_bounds__(512, 1)
attn_kernel(float* __restrict__ out) {
    extern __shared__ float sm[];
    float* Qt = sm;              // [256][64]  transposed, scaled by 16
    float* Kt = sm + 16384;      // [256][64]  transposed
    float* Vs = sm + 32768;      // [64][256]  natural
    float* Ps = sm + 49152;      // [64][64]

    const int b   = blockIdx.y;
    const int px  = blockIdx.x;        // 0..15
    const int tid = threadIdx.x;
    const int tx  = tid & 15;
    const int ty  = tid >> 4;          // 0..31

    const float* Kb = g_K + (size_t)b * NT * NH;
    const float* Vb = g_V + (size_t)b * NT * NH;

    const int li = tid & 63;    // row within tile for transposed loads
    const int hb = tid >> 6;    // 0..7

    for (int half = 0; half < 2; half++) {
        const int qt = (half == 0) ? (31 - px) : px;
        const float* Qg = g_Q + ((size_t)b * NT + qt * 64) * NH;

        __syncthreads();   // protect Qt from previous half's readers

        // load Q tile transposed, folding in the *sqrt(H)=16 logit scale
#pragma unroll
        for (int it = 0; it < 8; it++) {
            int h4 = (hb + 8 * it) * 4;
            float4 v = *(const float4*)(Qg + (size_t)li * NH + h4);
            Qt[(h4 + 0) * 64 + li] = v.x * 16.0f;
            Qt[(h4 + 1) * 64 + li] = v.y * 16.0f;
            Qt[(h4 + 2) * 64 + li] = v.z * 16.0f;
            Qt[(h4 + 3) * 64 + li] = v.w * 16.0f;
        }

        float m_run[2], l_run[2];
#pragma unroll
        for (int i = 0; i < 2; i++) { m_run[i] = -1e30f; l_run[i] = 0.0f; }

        u64 oacc[2][8];
#pragma unroll
        for (int i = 0; i < 2; i++)
#pragma unroll
            for (int j = 0; j < 8; j++) oacc[i][j] = 0ull;

        const int nIter = qt + 1;
        for (int itr = 0; itr < nIter; itr++) {
            const int j0 = itr * 64;
            __syncthreads();   // prior reads of Kt/Vs/Ps complete

            // load K tile transposed
#pragma unroll
            for (int it = 0; it < 8; it++) {
                int h4 = (hb + 8 * it) * 4;
                float4 v = *(const float4*)(Kb + (size_t)(j0 + li) * NH + h4);
                Kt[(h4 + 0) * 64 + li] = v.x;
                Kt[(h4 + 1) * 64 + li] = v.y;
                Kt[(h4 + 2) * 64 + li] = v.z;
                Kt[(h4 + 3) * 64 + li] = v.w;
            }
            // load V tile natural
#pragma unroll
            for (int it = 0; it < 8; it++) {
                int idx = it * 512 + tid;
                int j = idx >> 6, g4 = (idx & 63) * 4;
                *(float4*)&Vs[j * 256 + g4] =
                    *(const float4*)(Vb + (size_t)(j0 + j) * NH + g4);
            }
            __syncthreads();

            // ---- S = Q K^T (2x4 per thread, f32x2 over j-pairs) ----
            u64 sacc[2][2];
#pragma unroll
            for (int i = 0; i < 2; i++) { sacc[i][0] = 0ull; sacc[i][1] = 0ull; }
#pragma unroll 8
            for (int h = 0; h < 256; h++) {
                float2 q = *(const float2*)&Qt[h * 64 + 2 * ty];
                ulonglong2 kp = *(const ulonglong2*)&Kt[h * 64 + 4 * tx];
                u64 q0 = pack2(q.x, q.x);
                u64 q1 = pack2(q.y, q.y);
                fma2(sacc[0][0], q0, kp.x);
                fma2(sacc[0][1], q0, kp.y);
                fma2(sacc[1][0], q1, kp.x);
                fma2(sacc[1][1], q1, kp.y);
            }

            float s[2][4];
#pragma unroll
            for (int i = 0; i < 2; i++) {
                float2 p0 = unpack2(sacc[i][0]), p1 = unpack2(sacc[i][1]);
                s[i][0] = p0.x; s[i][1] = p0.y; s[i][2] = p1.x; s[i][3] = p1.y;
            }

            // causal mask (diagonal tile only)
            if (j0 == qt * 64) {
#pragma unroll
                for (int i = 0; i < 2; i++)
#pragma unroll
                    for (int j = 0; j < 4; j++)
                        if (4 * tx + j > 2 * ty + i) s[i][j] = -1e30f;
            }

            // ---- online softmax (stats replicated across the 16 tx lanes) ----
            float p[2][4];
#pragma unroll
            for (int i = 0; i < 2; i++) {
                float mloc = fmaxf(fmaxf(s[i][0], s[i][1]), fmaxf(s[i][2], s[i][3]));
#pragma unroll
                for (int off = 1; off < 16; off <<= 1)
                    mloc = fmaxf(mloc, __shfl_xor_sync(0xffffffffu, mloc, off, 16));
                float m_new = fmaxf(m_run[i], mloc);
                float scale = __expf(m_run[i] - m_new);
                float rsum = 0.0f;
#pragma unroll
                for (int j = 0; j < 4; j++) {
                    p[i][j] = __expf(s[i][j] - m_new);
                    rsum += p[i][j];
                }
#pragma unroll
                for (int off = 1; off < 16; off <<= 1)
                    rsum += __shfl_xor_sync(0xffffffffu, rsum, off, 16);
                l_run[i] = l_run[i] * scale + rsum;
                m_run[i] = m_new;
                u64 sc2 = pack2(scale, scale);
#pragma unroll
                for (int u = 0; u < 8; u++) mul2(oacc[i][u], sc2);
            }

            // stage P to smem
#pragma unroll
            for (int i = 0; i < 2; i++)
                *(float4*)&Ps[(2 * ty + i) * 64 + 4 * tx] =
                    make_float4(p[i][0], p[i][1], p[i][2], p[i][3]);
            __syncthreads();

            // ---- O += P V ----
#pragma unroll 4
            for (int j = 0; j < 64; j++) {
                ulonglong2 v0 = *(const ulonglong2*)&Vs[j * 256 + 4 * tx];
                ulonglong2 v1 = *(const ulonglong2*)&Vs[j * 256 + 4 * tx + 64];
                ulonglong2 v2 = *(const ulonglong2*)&Vs[j * 256 + 4 * tx + 128];
                ulonglong2 v3 = *(const ulonglong2*)&Vs[j * 256 + 4 * tx + 192];
#pragma unroll
                for (int i = 0; i < 2; i++) {
                    float pv = Ps[(2 * ty + i) * 64 + j];
                    u64 pp = pack2(pv, pv);
                    fma2(oacc[i][0], pp, v0.x); fma2(oacc[i][1], pp, v0.y);
                    fma2(oacc[i][2], pp, v1.x); fma2(oacc[i][3], pp, v1.y);
                    fma2(oacc[i][4], pp, v2.x); fma2(oacc[i][5], pp, v2.y);
                    fma2(oacc[i][6], pp, v3.x); fma2(oacc[i][7], pp, v3.y);
                }
            }
        }

        // ---- normalize + write ----
#pragma unroll
        for (int i = 0; i < 2; i++) {
            float inv = 1.0f / l_run[i];
            size_t row = (size_t)b * NT + qt * 64 + 2 * ty + i;
            float* orow = out + row * NH;
#pragma unroll
            for (int u = 0; u < 4; u++) {
                float2 a = unpack2(oacc[i][2 * u]);
                float2 c = unpack2(oacc[i][2 * u + 1]);
                *(float4*)(orow + 4 * tx + 64 * u) =
                    make_float4(a.x * inv, a.y * inv, c.x * inv, c.y * inv);
            }
        }
    }
}

extern "C" void kernel_launch(void* const* d_in, const int* in_sizes, int n_in,
                              void* d_out, int out_size) {
    const float* x  = (const float*)d_in[0];
    const float* Wq = (const float*)d_in[1];
    const float* Wk = (const float*)d_in[2];
    const float* Wv = (const float*)d_in[3];
    float* out = (float*)d_out;

    cudaFuncSetAttribute(attn_kernel,
                         cudaFuncAttributeMaxDynamicSharedMemorySize, ATTN_SMEM);

    qkv_kernel<<<dim3(2, 128, 3), 256>>>(x, Wq, Wk, Wv);
    attn_kernel<<<dim3(16, NB), 512, ATTN_SMEM>>>(out);
}